// round 3
// baseline (speedup 1.0000x reference)
#include <cuda_runtime.h>
#include <math.h>

// Problem constants (fixed by the reference)
#define N_TOK 4096
#define DIN   512
#define HDIM  2048
#define NEXP  8
#define TOPK  2
#define NSLOT (N_TOK * TOPK)   // 8192 token-expert slots

// -------- device scratch (no allocations allowed) --------
__device__ int   g_counts[NEXP];
__device__ int   g_list[NEXP * NSLOT];     // slot ids bucketed per expert
__device__ int   g_is64;                   // indices dtype flag
__device__ float g_h[(size_t)NSLOT * HDIM];  // 67 MB hidden activations
__device__ float g_y[(size_t)NSLOT * DIN];   // 16.8 MB per-slot outputs

// -------- kernel 0: reset counters + detect indices dtype --------
__global__ void k_reset(const int* idx32) {
    int t = threadIdx.x;
    if (t < NEXP) g_counts[t] = 0;
    if (t == 0) {
        // If int64 (little-endian, values 0..7): odd int32 words are all zero.
        // If int32: odd positions are expert ids for slot k=1 — all-zero is ~8^-16.
        int allz = 1;
        #pragma unroll
        for (int i = 1; i < 32; i += 2)
            if (idx32[i] != 0) allz = 0;
        g_is64 = allz;
    }
}

// -------- kernel 1: bucket slots by expert --------
__global__ void k_build(const void* idxp) {
    int s = blockIdx.x * blockDim.x + threadIdx.x;
    if (s >= NSLOT) return;
    int e;
    if (g_is64) e = (int)((const long long*)idxp)[s];
    else        e = ((const int*)idxp)[s];
    int pos = atomicAdd(&g_counts[e], 1);
    g_list[e * NSLOT + pos] = s;
}

__device__ __forceinline__ float gelu_tanh(float v) {
    float u = 0.7978845608028654f * (v + 0.044715f * v * v * v);
    return 0.5f * v * (1.0f + tanhf(u));
}

// -------- GEMM1: gather x rows -> h = gelu(x @ W1[e] + b1[e]) --------
// block tile 128(M) x 128(N), K-chunk 16, 256 threads, 8x8 per thread
__global__ __launch_bounds__(256, 2)
void k_gemm1(const float* __restrict__ x, const float* __restrict__ W1,
             const float* __restrict__ b1) {
    const int e   = blockIdx.z;
    const int cnt = g_counts[e];
    const int m0  = blockIdx.y * 128;
    if (m0 >= cnt) return;
    const int n0  = blockIdx.x * 128;

    __shared__ float As[16][132];
    __shared__ float Bs[16][132];

    const int tid  = threadIdx.x;
    const int arow = tid >> 1;          // 0..127
    const int ak   = (tid & 1) * 8;     // 0 or 8
    const float* arow_ptr = nullptr;
    if (m0 + arow < cnt) {
        int s = g_list[e * NSLOT + m0 + arow];
        arow_ptr = x + (size_t)(s >> 1) * DIN;   // token = slot/2
    }
    const int bk = tid >> 5;            // 0..7
    const int bn = (tid & 31) * 4;      // 0..124
    const float* Wbase = W1 + (size_t)e * DIN * HDIM;

    float acc[8][8];
    #pragma unroll
    for (int i = 0; i < 8; i++)
        #pragma unroll
        for (int j = 0; j < 8; j++) acc[i][j] = 0.0f;

    const int ty = tid >> 4, tx = tid & 15;

    for (int k0 = 0; k0 < DIN; k0 += 16) {
        float4 a0 = {0,0,0,0}, a1 = {0,0,0,0};
        if (arow_ptr) {
            a0 = *(const float4*)(arow_ptr + k0 + ak);
            a1 = *(const float4*)(arow_ptr + k0 + ak + 4);
        }
        As[ak + 0][arow] = a0.x; As[ak + 1][arow] = a0.y;
        As[ak + 2][arow] = a0.z; As[ak + 3][arow] = a0.w;
        As[ak + 4][arow] = a1.x; As[ak + 5][arow] = a1.y;
        As[ak + 6][arow] = a1.z; As[ak + 7][arow] = a1.w;
        #pragma unroll
        for (int kk = 0; kk < 2; kk++) {
            int kr = bk + kk * 8;
            *(float4*)&Bs[kr][bn] =
                *(const float4*)(Wbase + (size_t)(k0 + kr) * HDIM + n0 + bn);
        }
        __syncthreads();

        #pragma unroll
        for (int k = 0; k < 16; k++) {
            float ra[8], rb[8];
            *(float4*)&ra[0] = *(const float4*)&As[k][ty * 4];
            *(float4*)&ra[4] = *(const float4*)&As[k][64 + ty * 4];
            *(float4*)&rb[0] = *(const float4*)&Bs[k][tx * 4];
            *(float4*)&rb[4] = *(const float4*)&Bs[k][64 + tx * 4];
            #pragma unroll
            for (int i = 0; i < 8; i++)
                #pragma unroll
                for (int j = 0; j < 8; j++)
                    acc[i][j] = fmaf(ra[i], rb[j], acc[i][j]);
        }
        __syncthreads();
    }

    // epilogue: bias + gelu -> g_h[slot]
    #pragma unroll
    for (int i = 0; i < 8; i++) {
        int mloc = (i < 4) ? (ty * 4 + i) : (64 + ty * 4 + i - 4);
        int m = m0 + mloc;
        if (m >= cnt) continue;
        int s = g_list[e * NSLOT + m];
        float* hrow = g_h + (size_t)s * HDIM + n0;
        #pragma unroll
        for (int j = 0; j < 8; j++) {
            int n = (j < 4) ? (tx * 4 + j) : (64 + tx * 4 + j - 4);
            float v = acc[i][j] + b1[e * HDIM + n0 + n];
            hrow[n] = gelu_tanh(v);
        }
    }
}

// -------- GEMM2: gather h rows -> y = h @ W2[e] + b2[e] --------
__global__ __launch_bounds__(256, 2)
void k_gemm2(const float* __restrict__ W2, const float* __restrict__ b2) {
    const int e   = blockIdx.z;
    const int cnt = g_counts[e];
    const int m0  = blockIdx.y * 128;
    if (m0 >= cnt) return;
    const int n0  = blockIdx.x * 128;

    __shared__ float As[16][132];
    __shared__ float Bs[16][132];

    const int tid  = threadIdx.x;
    const int arow = tid >> 1;
    const int ak   = (tid & 1) * 8;
    const float* arow_ptr = nullptr;
    if (m0 + arow < cnt) {
        int s = g_list[e * NSLOT + m0 + arow];
        arow_ptr = g_h + (size_t)s * HDIM;
    }
    const int bk = tid >> 5;
    const int bn = (tid & 31) * 4;
    const float* Wbase = W2 + (size_t)e * HDIM * DIN;

    float acc[8][8];
    #pragma unroll
    for (int i = 0; i < 8; i++)
        #pragma unroll
        for (int j = 0; j < 8; j++) acc[i][j] = 0.0f;

    const int ty = tid >> 4, tx = tid & 15;

    for (int k0 = 0; k0 < HDIM; k0 += 16) {
        float4 a0 = {0,0,0,0}, a1 = {0,0,0,0};
        if (arow_ptr) {
            a0 = *(const float4*)(arow_ptr + k0 + ak);
            a1 = *(const float4*)(arow_ptr + k0 + ak + 4);
        }
        As[ak + 0][arow] = a0.x; As[ak + 1][arow] = a0.y;
        As[ak + 2][arow] = a0.z; As[ak + 3][arow] = a0.w;
        As[ak + 4][arow] = a1.x; As[ak + 5][arow] = a1.y;
        As[ak + 6][arow] = a1.z; As[ak + 7][arow] = a1.w;
        #pragma unroll
        for (int kk = 0; kk < 2; kk++) {
            int kr = bk + kk * 8;
            *(float4*)&Bs[kr][bn] =
                *(const float4*)(Wbase + (size_t)(k0 + kr) * DIN + n0 + bn);
        }
        __syncthreads();

        #pragma unroll
        for (int k = 0; k < 16; k++) {
            float ra[8], rb[8];
            *(float4*)&ra[0] = *(const float4*)&As[k][ty * 4];
            *(float4*)&ra[4] = *(const float4*)&As[k][64 + ty * 4];
            *(float4*)&rb[0] = *(const float4*)&Bs[k][tx * 4];
            *(float4*)&rb[4] = *(const float4*)&Bs[k][64 + tx * 4];
            #pragma unroll
            for (int i = 0; i < 8; i++)
                #pragma unroll
                for (int j = 0; j < 8; j++)
                    acc[i][j] = fmaf(ra[i], rb[j], acc[i][j]);
        }
        __syncthreads();
    }

    #pragma unroll
    for (int i = 0; i < 8; i++) {
        int mloc = (i < 4) ? (ty * 4 + i) : (64 + ty * 4 + i - 4);
        int m = m0 + mloc;
        if (m >= cnt) continue;
        int s = g_list[e * NSLOT + m];
        float* yrow = g_y + (size_t)s * DIN + n0;
        #pragma unroll
        for (int j = 0; j < 8; j++) {
            int n = (j < 4) ? (tx * 4 + j) : (64 + tx * 4 + j - 4);
            yrow[n] = acc[i][j] + b2[e * DIN + n0 + n];
        }
    }
}

// -------- combine: out[t] = p[t,0]*y[2t] + p[t,1]*y[2t+1] --------
__global__ void k_comb(const float* __restrict__ p, float* __restrict__ out) {
    int i = blockIdx.x * blockDim.x + threadIdx.x;   // over N*DIN/4
    if (i >= N_TOK * DIN / 4) return;
    int t  = i / (DIN / 4);
    int d4 = i % (DIN / 4);
    float p0 = p[t * 2], p1 = p[t * 2 + 1];
    float4 y0 = *(const float4*)(g_y + (size_t)(2 * t) * DIN + d4 * 4);
    float4 y1 = *(const float4*)(g_y + (size_t)(2 * t + 1) * DIN + d4 * 4);
    float4 o;
    o.x = p0 * y0.x + p1 * y1.x;
    o.y = p0 * y0.y + p1 * y1.y;
    o.z = p0 * y0.z + p1 * y1.z;
    o.w = p0 * y0.w + p1 * y1.w;
    *(float4*)(out + (size_t)i * 4) = o;
}

// -------- zero the tail of d_out (total_loss and any padding) --------
// The harness poisons d_out to 0xAA before timing; output 1 (the scalar
// loss, == 0.0f) lives past the N*D floats and must be written every call.
__global__ void k_tail(float* __restrict__ out, int begin, int total) {
    int i = begin + blockIdx.x * blockDim.x + threadIdx.x;
    if (i < total) out[i] = 0.0f;
}

extern "C" void kernel_launch(void* const* d_in, const int* in_sizes, int n_in,
                              void* d_out, int out_size) {
    const float* x    = (const float*)d_in[0];   // [N, D]
    const float* prob = (const float*)d_in[1];   // [N, K]
    const void*  idx  = d_in[2];                 // [N, K] int32 or int64
    const float* W1   = (const float*)d_in[3];   // [E, D, H]
    const float* b1   = (const float*)d_in[4];   // [E, H]
    const float* W2   = (const float*)d_in[5];   // [E, H, D]
    const float* b2   = (const float*)d_in[6];   // [E, D]
    float* out = (float*)d_out;                  // [N, D] + loss tail

    k_reset<<<1, 32>>>((const int*)idx);
    k_build<<<NSLOT / 256, 256>>>(idx);

    // GEMM1: n-tiles = H/128 = 16, m-tiles up to 8192/128 = 64, experts 8
    dim3 g1(HDIM / 128, NSLOT / 128, NEXP);
    k_gemm1<<<g1, 256>>>(x, W1, b1);

    // GEMM2: n-tiles = D/128 = 4
    dim3 g2(DIN / 128, NSLOT / 128, NEXP);
    k_gemm2<<<g2, 256>>>(W2, b2);

    k_comb<<<(N_TOK * DIN / 4 + 255) / 256, 256>>>(prob, out);

    // Zero everything past the [N, D] block (the loss scalar / padding).
    int tail = out_size - N_TOK * DIN;
    if (tail > 0) {
        int blocks = (tail + 255) / 256;
        k_tail<<<blocks, 256>>>(out, N_TOK * DIN, out_size);
    }
    (void)in_sizes; (void)n_in;
}